// round 3
// baseline (speedup 1.0000x reference)
#include <cuda_runtime.h>
#include <cuda_fp16.h>
#include <math.h>

#define Bc   4
#define C    48
#define C3   144
#define HH   256
#define WW   256
#define NPIX 65536   // HH*WW

typedef unsigned long long u64;

// packed f32x2 helpers (sm_100+: fma.rn.f32x2 — 2 fp32 FMAs per instruction)
__device__ __forceinline__ void ffma2(u64& d, u64 a, u64 b, u64 c) {
    asm("fma.rn.f32x2 %0, %1, %2, %3;" : "=l"(d) : "l"(a), "l"(b), "l"(c));
}
__device__ __forceinline__ u64 pack2(float x, float y) {
    u64 r; asm("mov.b64 %0, {%1, %2};" : "=l"(r) : "f"(x), "f"(y)); return r;
}
__device__ __forceinline__ void unpack2(float& x, float& y, u64 v) {
    asm("mov.b64 {%0, %1}, %2;" : "=f"(x), "=f"(y) : "l"(v));
}

// ---- scratch (device globals: no allocation allowed) ----
__device__ __half g_qkv[(size_t)Bc * C3 * NPIX];   // after 1x1 conv (75 MB)
__device__ __half g_dw [(size_t)Bc * C3 * NPIX];   // after depthwise (75 MB)
__device__ float  g_small[Bc * (C * C + 2 * C)];   // gram | qss | kss
__device__ float  g_M[Bc * C * C];                 // (proj @ attn)

// ============================================================
// K1: qkv 1x1 conv, FFMA2 packed over pixel pairs.
// ============================================================
__global__ __launch_bounds__(256) void k_qkv(const float* __restrict__ x,
                                             const float* __restrict__ w) {
    __shared__ float2 Ws2[C3 * C];  // duplicated (w,w): 55.3 KB
    const int tid = threadIdx.x;
    for (int i = tid; i < C3 * C; i += 256) { float v = w[i]; Ws2[i] = make_float2(v, v); }
    __syncthreads();

    const int blocksPerBatch = NPIX / 512;
    const int b = blockIdx.x / blocksPerBatch;
    const int pbase = (blockIdx.x % blocksPerBatch) * 512 + tid * 2;

    const float* xb = x + (size_t)b * C * NPIX + pbase;
    u64 xp[C];
#pragma unroll
    for (int ic = 0; ic < C; ic++)
        xp[ic] = *(const u64*)(xb + (size_t)ic * NPIX);

    __half* ob = g_qkv + (size_t)b * C3 * NPIX + pbase;
    for (int oc = 0; oc < C3; oc++) {
        const ulonglong2* wp = (const ulonglong2*)(Ws2 + oc * C);
        u64 a0 = 0ull, a1 = 0ull;
#pragma unroll
        for (int i = 0; i < C / 4; i++) {
            ulonglong2 w0 = wp[2 * i], w1 = wp[2 * i + 1];
            ffma2(a0, w0.x, xp[4 * i + 0], a0);
            ffma2(a1, w0.y, xp[4 * i + 1], a1);
            ffma2(a0, w1.x, xp[4 * i + 2], a0);
            ffma2(a1, w1.y, xp[4 * i + 3], a1);
        }
        float x0, y0, x1, y1;
        unpack2(x0, y0, a0); unpack2(x1, y1, a1);
        *(__half2*)(ob + (size_t)oc * NPIX) = __floats2half2_rn(x0 + x1, y0 + y1);
    }
}

// ============================================================
// K2: depthwise 3x3, pad 1. Block = (b,ch,8-row tile), 256 threads.
// half2 loads; each thread computes a 2-col pair -> half2 stores.
// ============================================================
#define DWROWS 8
__global__ __launch_bounds__(256) void k_dw(const float* __restrict__ w) {
    const int tilesY = HH / DWROWS;                  // 32
    const int ytile = blockIdx.x & (tilesY - 1);
    const int ch    = (blockIdx.x / tilesY) % C3;
    const int b     = blockIdx.x / (tilesY * C3);
    const int tid   = threadIdx.x;

    const __half* in  = g_qkv + ((size_t)b * C3 + ch) * NPIX;
    __half*       out = g_dw  + ((size_t)b * C3 + ch) * NPIX;

    __shared__ float rows[DWROWS + 2][WW];
    const int y0 = ytile * DWROWS;
    // 10 rows x 128 half2 = 1280 half2 loads, strided over 256 threads
    for (int i = tid; i < (DWROWS + 2) * (WW / 2); i += 256) {
        int r = i / (WW / 2), c2 = i % (WW / 2);
        int y = y0 - 1 + r;
        float2 v = make_float2(0.f, 0.f);
        if (y >= 0 && y < HH)
            v = __half22float2(*(const __half2*)(in + y * WW + 2 * c2));
        rows[r][2 * c2] = v.x; rows[r][2 * c2 + 1] = v.y;
    }
    __syncthreads();

    const float w00 = w[ch*9+0], w01 = w[ch*9+1], w02 = w[ch*9+2];
    const float w10 = w[ch*9+3], w11 = w[ch*9+4], w12 = w[ch*9+5];
    const float w20 = w[ch*9+6], w21 = w[ch*9+7], w22 = w[ch*9+8];

    const int half = tid >> 7;           // 0 or 1: row interleave
    const int c2   = tid & 127;          // column pair index
    const int col0 = 2 * c2, col1 = col0 + 1;
    const float lm = (c2 > 0) ? 1.f : 0.f;
    const float rm = (c2 < 127) ? 1.f : 0.f;
    const int xl = max(col0 - 1, 0), xr = min(col1 + 1, WW - 1);

#pragma unroll
    for (int rr = 0; rr < DWROWS / 2; rr++) {
        const int r = 2 * rr + half;
        float a0, b0, cc0, d0;
        float acc0 = 0.f, acc1 = 0.f;
#pragma unroll
        for (int k = 0; k < 3; k++) {
            const float* rw = rows[r + k];
            a0 = rw[xl] * lm; b0 = rw[col0]; cc0 = rw[col1]; d0 = rw[xr] * rm;
            const float wk0 = w[0], wk1 = w[0]; // placeholder (unused)
            float ww0 = (k == 0) ? w00 : (k == 1) ? w10 : w20;
            float ww1 = (k == 0) ? w01 : (k == 1) ? w11 : w21;
            float ww2 = (k == 0) ? w02 : (k == 1) ? w12 : w22;
            acc0 += ww0 * a0 + ww1 * b0 + ww2 * cc0;
            acc1 += ww0 * b0 + ww1 * cc0 + ww2 * d0;
            (void)wk0; (void)wk1;
        }
        *(__half2*)(out + (y0 + r) * WW + col0) = __floats2half2_rn(acc0, acc1);
    }
}

// ============================================================
// K3: Gram G = Q K^T (48x48) + squared norms; FFMA2 over pixel pairs.
// 16x16 threads, 3x3 register block of packed accumulators.
// ============================================================
#define TS2   32     // float2 elements per smem row (64 pixels)
#define CHUNK 1024
__global__ __launch_bounds__(256) void k_gram() {
    const int chunks = NPIX / CHUNK;  // 64
    const int b     = blockIdx.x / chunks;
    const int cbase = (blockIdx.x % chunks) * CHUNK;

    __shared__ float2 Qs[C][TS2 + 1], Ks[C][TS2 + 1];
    const int tid = threadIdx.x;
    const int c0 = (tid >> 4) * 3;
    const int d0 = (tid & 15) * 3;

    const __half* Q = g_dw + (size_t)b * C3 * NPIX;
    const __half* K = g_dw + (size_t)b * C3 * NPIX + (size_t)C * NPIX;

    u64 acc[3][3]; 
#pragma unroll
    for (int i = 0; i < 3; i++)
#pragma unroll
        for (int j = 0; j < 3; j++) acc[i][j] = 0ull;
    u64 sqa = 0ull;

    for (int sub = 0; sub < CHUNK / (2 * TS2); sub++) {
        const int tb = cbase + sub * (2 * TS2);
        for (int i = tid; i < C * TS2; i += 256) {
            int cc = i / TS2, t = i % TS2;
            Qs[cc][t] = __half22float2(*(const __half2*)(Q + (size_t)cc * NPIX + tb + 2 * t));
            Ks[cc][t] = __half22float2(*(const __half2*)(K + (size_t)cc * NPIX + tb + 2 * t));
        }
        __syncthreads();
#pragma unroll 4
        for (int t = 0; t < TS2; t++) {
            u64 q0 = *(const u64*)&Qs[c0][t];
            u64 q1 = *(const u64*)&Qs[c0 + 1][t];
            u64 q2 = *(const u64*)&Qs[c0 + 2][t];
            u64 k0 = *(const u64*)&Ks[d0][t];
            u64 k1 = *(const u64*)&Ks[d0 + 1][t];
            u64 k2 = *(const u64*)&Ks[d0 + 2][t];
            ffma2(acc[0][0], q0, k0, acc[0][0]); ffma2(acc[0][1], q0, k1, acc[0][1]); ffma2(acc[0][2], q0, k2, acc[0][2]);
            ffma2(acc[1][0], q1, k0, acc[1][0]); ffma2(acc[1][1], q1, k1, acc[1][1]); ffma2(acc[1][2], q1, k2, acc[1][2]);
            ffma2(acc[2][0], q2, k0, acc[2][0]); ffma2(acc[2][1], q2, k1, acc[2][1]); ffma2(acc[2][2], q2, k2, acc[2][2]);
            if (tid < C)          { u64 v = *(const u64*)&Qs[tid][t];     ffma2(sqa, v, v, sqa); }
            else if (tid < 2 * C) { u64 v = *(const u64*)&Ks[tid - C][t]; ffma2(sqa, v, v, sqa); }
        }
        __syncthreads();
    }

    float* gbase = g_small + b * (C * C + 2 * C);
#pragma unroll
    for (int i = 0; i < 3; i++)
#pragma unroll
        for (int j = 0; j < 3; j++) {
            float lo, hi; unpack2(lo, hi, acc[i][j]);
            atomicAdd(&gbase[(c0 + i) * C + (d0 + j)], lo + hi);
        }
    if (tid < 2 * C) { float lo, hi; unpack2(lo, hi, sqa); atomicAdd(&gbase[C * C + tid], lo + hi); }
}

// ============================================================
// K4: softmax(G/(qn*kn)*T) then M = proj @ attn. One block per batch.
// ============================================================
__global__ __launch_bounds__(256) void k_attn(const float* __restrict__ proj,
                                              const float* __restrict__ temp) {
    const int b = blockIdx.x;
    const int tid = threadIdx.x;
    const int warp = tid >> 5, lane = tid & 31;
    __shared__ float A[C][C + 1];
    __shared__ float P[C * C];
    __shared__ float qn[C], kn[C];
    const float* gbase = g_small + b * (C * C + 2 * C);
    const float T = temp[0];

    for (int i = tid; i < C * C; i += 256) P[i] = proj[i];
    if (tid < C)          qn[tid]     = fmaxf(sqrtf(gbase[C * C + tid]), 1e-12f);
    else if (tid < 2 * C) kn[tid - C] = fmaxf(sqrtf(gbase[C * C + tid]), 1e-12f);
    __syncthreads();

    for (int i = tid; i < C * C; i += 256) {
        int r = i / C, d = i % C;
        A[r][d] = gbase[i] * T / (qn[r] * kn[d]);
    }
    __syncthreads();

    for (int r = warp; r < C; r += 8) {
        float v0 = A[r][lane];
        float v1 = (lane + 32 < C) ? A[r][lane + 32] : -1e30f;
        float mx = fmaxf(v0, v1);
#pragma unroll
        for (int o = 16; o > 0; o >>= 1) mx = fmaxf(mx, __shfl_xor_sync(~0u, mx, o));
        float e0 = expf(v0 - mx);
        float e1 = (lane + 32 < C) ? expf(v1 - mx) : 0.f;
        float s = e0 + e1;
#pragma unroll
        for (int o = 16; o > 0; o >>= 1) s += __shfl_xor_sync(~0u, s, o);
        float inv = 1.f / s;
        A[r][lane] = e0 * inv;
        if (lane + 32 < C) A[r][lane + 32] = e1 * inv;
    }
    __syncthreads();

    for (int i = tid; i < C * C; i += 256) {
        const int oc = i / C, d = i % C;
        float a = 0.f;
#pragma unroll
        for (int cc = 0; cc < C; cc++) a += P[oc * C + cc] * A[cc][d];
        g_M[b * C * C + i] = a;
    }
}

// ============================================================
// K5: out = M @ V, FFMA2 packed; writes d_out (fp32).
// ============================================================
__global__ __launch_bounds__(256) void k_out(float* __restrict__ out) {
    __shared__ float2 Ms2[C * C];  // duplicated (m,m): 18.4 KB
    const int tid = threadIdx.x;
    const int blocksPerBatch = NPIX / 512;
    const int b = blockIdx.x / blocksPerBatch;
    const int pbase = (blockIdx.x % blocksPerBatch) * 512 + tid * 2;

    for (int i = tid; i < C * C; i += 256) { float v = g_M[b * C * C + i]; Ms2[i] = make_float2(v, v); }
    __syncthreads();

    const __half* vb = g_dw + (size_t)b * C3 * NPIX + (size_t)(2 * C) * NPIX + pbase;
    u64 vp[C];
#pragma unroll
    for (int cc = 0; cc < C; cc++) {
        float2 t = __half22float2(*(const __half2*)(vb + (size_t)cc * NPIX));
        vp[cc] = pack2(t.x, t.y);
    }

    float* ob = out + (size_t)b * C * NPIX + pbase;
    for (int oc = 0; oc < C; oc++) {
        const ulonglong2* mp = (const ulonglong2*)(Ms2 + oc * C);
        u64 a0 = 0ull, a1 = 0ull;
#pragma unroll
        for (int i = 0; i < C / 4; i++) {
            ulonglong2 m0 = mp[2 * i], m1 = mp[2 * i + 1];
            ffma2(a0, m0.x, vp[4 * i + 0], a0);
            ffma2(a1, m0.y, vp[4 * i + 1], a1);
            ffma2(a0, m1.x, vp[4 * i + 2], a0);
            ffma2(a1, m1.y, vp[4 * i + 3], a1);
        }
        float x0, y0, x1, y1;
        unpack2(x0, y0, a0); unpack2(x1, y1, a1);
        float2 o; o.x = x0 + x1; o.y = y0 + y1;
        *(float2*)(ob + (size_t)oc * NPIX) = o;
    }
}

// ============================================================
extern "C" void kernel_launch(void* const* d_in, const int* in_sizes, int n_in,
                              void* d_out, int out_size) {
    const float* x      = (const float*)d_in[0];
    const float* qkv_w  = (const float*)d_in[1];
    const float* dw_w   = (const float*)d_in[2];
    const float* proj_w = (const float*)d_in[3];
    const float* temp   = (const float*)d_in[4];

    void* smallp = nullptr;
    cudaGetSymbolAddress(&smallp, g_small);
    cudaMemsetAsync(smallp, 0, sizeof(float) * Bc * (C * C + 2 * C));

    k_qkv <<<Bc * (NPIX / 512),          256>>>(x, qkv_w);
    k_dw  <<<Bc * C3 * (HH / DWROWS),    256>>>(dw_w);
    k_gram<<<Bc * (NPIX / CHUNK),        256>>>();
    k_attn<<<Bc,                         256>>>(proj_w, temp);
    k_out <<<Bc * (NPIX / 512),          256>>>((float*)d_out);
}